// round 2
// baseline (speedup 1.0000x reference)
#include <cuda_runtime.h>
#include <cstdint>

// Problem constants
#define BB   16
#define HH   128
#define WW   128
#define CC   64    // CIN
#define FF   128   // F
#define KK   3

typedef unsigned long long ull;

__device__ __forceinline__ ull pk2(float x, float y) {
    ull r; asm("mov.b64 %0, {%1, %2};" : "=l"(r) : "f"(x), "f"(y)); return r;
}
__device__ __forceinline__ void upk2(ull v, float& x, float& y) {
    asm("mov.b64 {%0, %1}, %2;" : "=f"(x), "=f"(y) : "l"(v));
}
// Packed dual-FMA (sm_100+): lo = fma(a.lo,b.lo,c.lo), hi likewise. Exact fp32.
__device__ __forceinline__ ull ffma2(ull a, ull b, ull c) {
    ull d; asm("fma.rn.f32x2 %0, %1, %2, %3;" : "=l"(d) : "l"(a), "l"(b), "l"(c)); return d;
}

// smem layout (floats):
//   Ar [64c][65]   (padded stride: conflict-free transpose writes + reads)
//   Ai [64c][65]
//   Kr [64c][128f]
//   Ki [64c][128f]
#define A_STR 65
#define A_SZ  (CC * A_STR)          // 4160 floats
#define KW_SZ (CC * FF)             // 8192 floats
#define SMEM_FLOATS (2*A_SZ + 2*KW_SZ)  // 24704 floats = 98816 bytes

__global__ __launch_bounds__(256, 2)
void cconv_kernel(const float* __restrict__ xr, const float* __restrict__ xi,
                  const float* __restrict__ kr, const float* __restrict__ ki,
                  const float* __restrict__ br, const float* __restrict__ bi,
                  float* __restrict__ out)
{
    extern __shared__ float smem[];
    float* Ar = smem;
    float* Ai = smem + A_SZ;
    float* Kr = smem + 2*A_SZ;
    float* Ki = smem + 2*A_SZ + KW_SZ;

    const int tid  = threadIdx.x;
    const int lane = tid & 31;
    const int warp = tid >> 5;
    const int fbase = warp * 16;       // 8 warps x 16 F columns

    const int wt = blockIdx.x;         // 0..1   (w tile)
    const int h  = blockIdx.y;         // 0..127
    const int b  = blockIdx.z;         // 0..15
    const int w0 = wt * 64;

    // accumulators: 2 pixels x 8 f-pairs, packed f32x2, real & imag
    ull accR[2][8], accI[2][8];
    #pragma unroll
    for (int p = 0; p < 2; ++p)
        #pragma unroll
        for (int j = 0; j < 8; ++j) { accR[p][j] = 0ull; accI[p][j] = 0ull; }

    #pragma unroll 1
    for (int slab = 0; slab < 9; ++slab) {
        const int kh = slab / 3, kw = slab % 3;
        const int h2 = h + kh - 1;
        __syncthreads();   // protect smem from previous slab's consumers

        // ---- load A tiles: 64 pixels x 64 channels, transposed to [c][p] ----
        {
            const bool hok = ((unsigned)h2 < (unsigned)HH);
            const float4* xr4 = (const float4*)xr;
            const float4* xi4 = (const float4*)xi;
            #pragma unroll
            for (int it = 0; it < 4; ++it) {
                int j  = tid + it * 256;        // 0..1023
                int p  = j >> 4;                // 0..63
                int c4 = j & 15;                // 0..15
                int w2 = w0 + p + kw - 1;
                float4 vr = make_float4(0.f,0.f,0.f,0.f);
                float4 vi = vr;
                if (hok && ((unsigned)w2 < (unsigned)WW)) {
                    long base = ((((long)b*HH + h2)*WW + w2)*CC >> 2) + c4;
                    vr = xr4[base];
                    vi = xi4[base];
                }
                int c = c4 * 4;
                Ar[(c+0)*A_STR + p] = vr.x; Ar[(c+1)*A_STR + p] = vr.y;
                Ar[(c+2)*A_STR + p] = vr.z; Ar[(c+3)*A_STR + p] = vr.w;
                Ai[(c+0)*A_STR + p] = vi.x; Ai[(c+1)*A_STR + p] = vi.y;
                Ai[(c+2)*A_STR + p] = vi.z; Ai[(c+3)*A_STR + p] = vi.w;
            }
        }
        // ---- load weight tiles: 64 c x 128 f (same layout, straight copy) ----
        {
            const float4* kr4 = (const float4*)(kr + (long)slab * CC * FF);
            const float4* ki4 = (const float4*)(ki + (long)slab * CC * FF);
            float4* Kr4 = (float4*)Kr;
            float4* Ki4 = (float4*)Ki;
            #pragma unroll
            for (int it = 0; it < 8; ++it) {
                int j = tid + it * 256;         // 0..2047
                Kr4[j] = kr4[j];
                Ki4[j] = ki4[j];
            }
        }
        __syncthreads();

        // ---- inner product over 64 channels ----
        const ull* Kr2 = (const ull*)Kr;
        const ull* Ki2 = (const ull*)Ki;
        #pragma unroll 2
        for (int c = 0; c < CC; ++c) {
            float ar0s = Ar[c*A_STR + lane];
            float ar1s = Ar[c*A_STR + lane + 32];
            float ai0s = Ai[c*A_STR + lane];
            float ai1s = Ai[c*A_STR + lane + 32];
            ull ar0  = pk2(ar0s, ar0s),   ar1  = pk2(ar1s, ar1s);
            ull ai0  = pk2(ai0s, ai0s),   ai1  = pk2(ai1s, ai1s);
            ull nai0 = pk2(-ai0s, -ai0s), nai1 = pk2(-ai1s, -ai1s);
            const ull* krow = Kr2 + c*64 + (fbase >> 1);
            const ull* kiow = Ki2 + c*64 + (fbase >> 1);
            #pragma unroll
            for (int jj = 0; jj < 8; ++jj) {
                ull k_r = krow[jj];     // broadcast LDS.64 (f, f+1)
                ull k_i = kiow[jj];
                // real = xr*kr + (-xi)*ki ; imag = xr*ki + xi*kr
                accR[0][jj] = ffma2(ar0,  k_r, accR[0][jj]);
                accR[0][jj] = ffma2(nai0, k_i, accR[0][jj]);
                accI[0][jj] = ffma2(ar0,  k_i, accI[0][jj]);
                accI[0][jj] = ffma2(ai0,  k_r, accI[0][jj]);
                accR[1][jj] = ffma2(ar1,  k_r, accR[1][jj]);
                accR[1][jj] = ffma2(nai1, k_i, accR[1][jj]);
                accI[1][jj] = ffma2(ar1,  k_i, accI[1][jj]);
                accI[1][jj] = ffma2(ai1,  k_r, accI[1][jj]);
            }
        }
    }

    // ---- epilogue: bias + store both planes ----
    const long planeStride = (long)BB * HH * WW * FF;
    #pragma unroll
    for (int p = 0; p < 2; ++p) {
        int w = w0 + lane + p * 32;
        long base = (((long)b*HH + h)*WW + w)*FF + fbase;
        #pragma unroll
        for (int j = 0; j < 8; ++j) {
            float r0, r1, i0, i1;
            upk2(accR[p][j], r0, r1);
            upk2(accI[p][j], i0, i1);
            int f = fbase + 2*j;
            r0 += br[f]; r1 += br[f+1];
            i0 += bi[f]; i1 += bi[f+1];
            *(float2*)(out + base + 2*j)               = make_float2(r0, r1);
            *(float2*)(out + planeStride + base + 2*j) = make_float2(i0, i1);
        }
    }
}

extern "C" void kernel_launch(void* const* d_in, const int* in_sizes, int n_in,
                              void* d_out, int out_size) {
    const float* xr = (const float*)d_in[0];
    const float* xi = (const float*)d_in[1];
    const float* kr = (const float*)d_in[2];
    const float* ki = (const float*)d_in[3];
    const float* br = (const float*)d_in[4];
    const float* bi = (const float*)d_in[5];
    float* out = (float*)d_out;

    (void)in_sizes; (void)n_in; (void)out_size;

    // dynamic smem > 48KB needs an opt-in; idempotent, capture-safe (no stream op)
    cudaFuncSetAttribute(cconv_kernel,
                         cudaFuncAttributeMaxDynamicSharedMemorySize,
                         SMEM_FLOATS * sizeof(float));

    dim3 grid(WW / 64, HH, BB);   // (2, 128, 16) = 4096 blocks
    cconv_kernel<<<grid, 256, SMEM_FLOATS * sizeof(float)>>>(
        xr, xi, kr, ki, br, bi, out);
}

// round 4
// speedup vs baseline: 2.0720x; 2.0720x over previous
#include <cuda_runtime.h>
#include <cuda_bf16.h>
#include <cstdint>

#define BB 16
#define HH 128
#define WW 128
#define CC 64
#define FF 128

// ---- dynamic smem layout (bytes) ----
#define OFF_BIAS 0            // 256 floats = 1 KB
#define OFF_AHI  1024         // 32 KB : [128 m][256B row], swizzled 16B chunks
#define OFF_ALO  (OFF_AHI + 32768)
#define OFF_B0   (OFF_ALO + 32768)   // 64 KB : [256 n][256B row], swizzled
#define OFF_B1   (OFF_B0 + 65536)
#define DYN_SMEM (OFF_B1 + 65536)    // 197632 B

// ---- global scratch ----
// per pixel 512B: [xr_hi 64bf][xi_hi 64bf][xr_lo 64bf][xi_lo 64bf]
__device__ __align__(16) unsigned char g_xsplit[(size_t)BB*HH*WW*512];
// per (tap,part): [256 n][128 k] bf16 rows, pre-swizzled; 64KB each
__device__ __align__(16) unsigned char g_bimg[9*2*65536];

// ---------------- helpers ----------------
__device__ __forceinline__ uint32_t smem_u32(const void* p) {
    uint32_t a;
    asm("{ .reg .u64 t; cvta.to.shared.u64 t, %1; cvt.u32.u64 %0, t; }" : "=r"(a) : "l"(p));
    return a;
}
__device__ __forceinline__ void cpa16(uint32_t dst, const void* src, int sz) {
    asm volatile("cp.async.cg.shared.global [%0], [%1], 16, %2;\n"
                 :: "r"(dst), "l"(src), "r"(sz) : "memory");
}
__device__ __forceinline__ void cpa_commit() {
    asm volatile("cp.async.commit_group;\n" ::: "memory");
}
__device__ __forceinline__ void cpa_wait0() {
    asm volatile("cp.async.wait_group 0;\n" ::: "memory");
}
__device__ __forceinline__ void ldsm4(uint32_t& r0, uint32_t& r1, uint32_t& r2, uint32_t& r3,
                                      uint32_t addr) {
    asm volatile("ldmatrix.sync.aligned.m8n8.x4.shared.b16 {%0,%1,%2,%3}, [%4];"
                 : "=r"(r0), "=r"(r1), "=r"(r2), "=r"(r3) : "r"(addr));
}
__device__ __forceinline__ void mma_bf16(float* d, const uint32_t* a, uint32_t b0, uint32_t b1) {
    asm volatile("mma.sync.aligned.m16n8k16.row.col.f32.bf16.bf16.f32 "
                 "{%0,%1,%2,%3}, {%4,%5,%6,%7}, {%8,%9}, {%0,%1,%2,%3};"
                 : "+f"(d[0]), "+f"(d[1]), "+f"(d[2]), "+f"(d[3])
                 : "r"(a[0]), "r"(a[1]), "r"(a[2]), "r"(a[3]), "r"(b0), "r"(b1));
}

// ---------------- prep kernels ----------------
__global__ void prep_x(const float* __restrict__ xr, const float* __restrict__ xi) {
    int t = blockIdx.x * blockDim.x + threadIdx.x;   // pixel*16 + quad
    int pix = t >> 4, q = t & 15;
    const float4 r4 = *(const float4*)(xr + (size_t)pix * CC + q * 4);
    const float4 i4 = *(const float4*)(xi + (size_t)pix * CC + q * 4);
    float v[8] = {r4.x, r4.y, r4.z, r4.w, i4.x, i4.y, i4.z, i4.w};
    unsigned short h[8], l[8];
    #pragma unroll
    for (int j = 0; j < 8; ++j) {
        __nv_bfloat16 hb = __float2bfloat16(v[j]);
        __nv_bfloat16 lb = __float2bfloat16(v[j] - __bfloat162float(hb));
        h[j] = *(unsigned short*)&hb;
        l[j] = *(unsigned short*)&lb;
    }
    unsigned char* p = g_xsplit + (size_t)pix * 512;
    uint2 rh = make_uint2((uint32_t)h[0] | ((uint32_t)h[1] << 16), (uint32_t)h[2] | ((uint32_t)h[3] << 16));
    uint2 ih = make_uint2((uint32_t)h[4] | ((uint32_t)h[5] << 16), (uint32_t)h[6] | ((uint32_t)h[7] << 16));
    uint2 rl = make_uint2((uint32_t)l[0] | ((uint32_t)l[1] << 16), (uint32_t)l[2] | ((uint32_t)l[3] << 16));
    uint2 il = make_uint2((uint32_t)l[4] | ((uint32_t)l[5] << 16), (uint32_t)l[6] | ((uint32_t)l[7] << 16));
    *(uint2*)(p +   0 + q * 8) = rh;
    *(uint2*)(p + 128 + q * 8) = ih;
    *(uint2*)(p + 256 + q * 8) = rl;
    *(uint2*)(p + 384 + q * 8) = il;
}

// B image: per (tap, part): rows n=0..255, each 256B (128 k bf16),
// 16B chunk c stored at c ^ (n & 7).   Column n<128 -> real out, n>=128 -> imag.
// k<64 -> xr channels, k>=64 -> xi channels.
__global__ void prep_b(const float* __restrict__ kr, const float* __restrict__ ki) {
    int idx = blockIdx.x * blockDim.x + threadIdx.x;
    if (idx >= 9 * 2 * 256 * 128) return;
    int k    = idx & 127;
    int n    = (idx >> 7) & 255;
    int part = (idx >> 15) & 1;
    int t    = idx >> 16;
    int c = k & 63;
    int f = n & 127;
    bool kSecond = k >= 64;
    bool imagOut = n >= 128;
    const float* src;
    float sign = 1.0f;
    if (!imagOut) { if (!kSecond) src = kr; else { src = ki; sign = -1.0f; } }
    else          { if (!kSecond) src = ki; else   src = kr; }
    float w = sign * src[((size_t)t * 64 + c) * 128 + f];
    __nv_bfloat16 hb = __float2bfloat16(w);
    __nv_bfloat16 lb = __float2bfloat16(w - __bfloat162float(hb));
    __nv_bfloat16 val = part ? lb : hb;
    uint32_t off = (uint32_t)n * 256 + (uint32_t)(((k >> 3) ^ (n & 7)) * 16) + (k & 7) * 2;
    *(__nv_bfloat16*)(g_bimg + ((size_t)(t * 2 + part) << 16) + off) = val;
}

// ---------------- main kernel ----------------
__global__ __launch_bounds__(256, 1)
void cconv_hmma(const float* __restrict__ br, const float* __restrict__ bi,
                float* __restrict__ out)
{
    extern __shared__ unsigned char sb[];
    const uint32_t base = smem_u32(sb);

    const int tid  = threadIdx.x;
    const int lane = tid & 31;
    const int warp = tid >> 5;
    const int wm   = warp & 3;       // 0..3  -> M offset wm*32
    const int wn   = warp >> 2;      // 0..1  -> N offset wn*128
    const int h = blockIdx.x;
    const int b = blockIdx.y;

    // bias to smem
    *(float*)(sb + OFF_BIAS + tid * 4) = (tid < 128) ? br[tid] : bi[tid - 128];
    __syncthreads();

    float acc[2][16][4];
    #pragma unroll
    for (int mt = 0; mt < 2; ++mt)
        #pragma unroll
        for (int nt = 0; nt < 16; ++nt)
            #pragma unroll
            for (int j = 0; j < 4; ++j) acc[mt][nt][j] = 0.f;

    // per-lane ldmatrix base addressing
    const int lrow = lane & 15;          // matrix row within 16
    const int lhi  = lane >> 4;          // 0: k0-7 chunk, 1: k8-15 chunk
    const int lsw  = lane & 7;           // row&7 for swizzle (same for A and B rows)
    const uint32_t aRowOff0 = (uint32_t)(wm * 32 + lrow) * 256;
    const uint32_t aRowOff1 = aRowOff0 + 16 * 256;
    const uint32_t bRowBase = (uint32_t)(wn * 128 + lrow) * 256;

    // one GEMM pass: D += A(aOff) * B(bOff), K=128
    auto do_pass = [&](uint32_t aOff, uint32_t bOff) {
        #pragma unroll
        for (int kk = 0; kk < 8; ++kk) {
            const uint32_t swc = (uint32_t)(((2 * kk + lhi) ^ lsw) * 16);
            uint32_t a[2][4];
            ldsm4(a[0][0], a[0][1], a[0][2], a[0][3], base + aOff + aRowOff0 + swc);
            ldsm4(a[1][0], a[1][1], a[1][2], a[1][3], base + aOff + aRowOff1 + swc);
            #pragma unroll
            for (int nt2 = 0; nt2 < 8; ++nt2) {
                uint32_t r0, r1, r2, r3;
                ldsm4(r0, r1, r2, r3, base + bOff + bRowBase + (uint32_t)(nt2 * 16 * 256) + swc);
                // n-lo frag {r0,r2}, n-hi frag {r1,r3}
                mma_bf16(acc[0][2*nt2],   a[0], r0, r2);
                mma_bf16(acc[0][2*nt2+1], a[0], r1, r3);
                mma_bf16(acc[1][2*nt2],   a[1], r0, r2);
                mma_bf16(acc[1][2*nt2+1], a[1], r1, r3);
            }
        }
    };

    auto load_B = [&](uint32_t dstOff, int tap, int part) {
        const unsigned char* src = g_bimg + (((size_t)(tap * 2 + part)) << 16);
        #pragma unroll
        for (int it = 0; it < 16; ++it) {
            int idx = tid + it * 256;
            cpa16(base + dstOff + (uint32_t)idx * 16, src + (size_t)idx * 16, 16);
        }
    };

    // prologue: start Bhi(tap0) into B0
    load_B(OFF_B0, 0, 0);

    #pragma unroll 1
    for (int tap = 0; tap < 9; ++tap) {
        const int kh = tap / 3, kw = tap % 3;
        const int h2 = h + kh - 1;
        const bool valid = ((unsigned)h2 < (unsigned)HH);

        if (valid) {
            const unsigned char* rowbase = g_xsplit + ((size_t)(b * HH + h2) * WW) * 512;
            #pragma unroll
            for (int it = 0; it < 16; ++it) {
                int idx  = tid + it * 256;        // 0..4095
                int part = idx >> 11;
                int rem  = idx & 2047;
                int m    = rem >> 4;
                int ch   = rem & 15;
                int w2 = m + kw - 1;
                int sz = ((unsigned)w2 < (unsigned)WW) ? 16 : 0;
                int w2c = min(max(w2, 0), WW - 1);
                const void* src = rowbase + (size_t)w2c * 512 + part * 256 + ch * 16;
                uint32_t dst = base + (part ? OFF_ALO : OFF_AHI)
                             + (uint32_t)m * 256 + (uint32_t)((ch ^ (m & 7)) * 16);
                cpa16(dst, src, sz);
            }
        }
        cpa_commit();
        cpa_wait0();            // A(tap) + Bhi(tap) ready
        __syncthreads();

        load_B(OFF_B1, tap, 1); // Blo(tap) overlaps the 2 hi-B passes
        cpa_commit();

        if (valid) {
            do_pass(OFF_AHI, OFF_B0);
            do_pass(OFF_ALO, OFF_B0);
        }
        cpa_wait0();            // Blo ready
        __syncthreads();        // everyone done reading B0

        if (tap < 8) {          // prefetch next Bhi under pass 3
            load_B(OFF_B0, tap + 1, 0);
            cpa_commit();
        }
        if (valid) do_pass(OFF_AHI, OFF_B1);
    }

    // ---- epilogue: bias + direct stores ----
    const size_t planeStride = (size_t)BB * HH * WW * FF;
    const size_t pixrow = ((size_t)(b * HH + h) * WW) * FF;
    const float* bias_s = (const float*)(sb + OFF_BIAS);
    #pragma unroll
    for (int mt = 0; mt < 2; ++mt) {
        int r0 = wm * 32 + mt * 16 + (lane >> 2);
        #pragma unroll
        for (int nt = 0; nt < 16; ++nt) {
            int col = wn * 128 + nt * 8 + (lane & 3) * 2;
            float2 bv = *(const float2*)(bias_s + col);
            int plane = col >> 7;
            int f = col & 127;
            float* o0 = out + (size_t)plane * planeStride + pixrow + (size_t)r0 * FF + f;
            *(float2*)o0 = make_float2(acc[mt][nt][0] + bv.x, acc[mt][nt][1] + bv.y);
            *(float2*)(o0 + 8 * FF) = make_float2(acc[mt][nt][2] + bv.x, acc[mt][nt][3] + bv.y);
        }
    }
}

// ---------------- launch ----------------
extern "C" void kernel_launch(void* const* d_in, const int* in_sizes, int n_in,
                              void* d_out, int out_size) {
    const float* xr = (const float*)d_in[0];
    const float* xi = (const float*)d_in[1];
    const float* kr = (const float*)d_in[2];
    const float* ki = (const float*)d_in[3];
    const float* br = (const float*)d_in[4];
    const float* bi = (const float*)d_in[5];
    float* out = (float*)d_out;
    (void)in_sizes; (void)n_in; (void)out_size;

    cudaFuncSetAttribute(cconv_hmma, cudaFuncAttributeMaxDynamicSharedMemorySize, DYN_SMEM);

    prep_x<<<(BB * HH * WW * 16) / 256, 256>>>(xr, xi);
    prep_b<<<(9 * 2 * 256 * 128 + 255) / 256, 256>>>(kr, ki);
    cconv_hmma<<<dim3(HH, BB), 256, DYN_SMEM>>>(br, bi, out);
}

// round 6
// speedup vs baseline: 2.7423x; 1.3235x over previous
#include <cuda_runtime.h>
#include <cuda_fp16.h>
#include <cstdint>

#define BB 16
#define HH 128
#define WW 128
#define CC 64
#define FF 128

// ---- dynamic smem layout (bytes) ----
#define OFF_BIAS 0                 // 256 floats = 1 KB
#define OFF_A0   1024              // buf0: [hi 32KB][lo 32KB]
#define OFF_A1   (OFF_A0 + 65536)  // buf1
#define OFF_B    (OFF_A1 + 65536)  // 64 KB : [256 n][256B row], swizzled
#define DYN_SMEM (OFF_B + 65536)   // 197632 B

// ---- global scratch ----
// per pixel 512B: [xr_hi 128B][xi_hi 128B][xr_lo 128B][xi_lo 128B]  (fp16)
__device__ __align__(16) unsigned char g_xsplit[(size_t)BB*HH*WW*512];
// per tap: [256 n][128 k] fp16 rows, pre-swizzled; 64KB each
__device__ __align__(16) unsigned char g_bimg[9*65536];

// ---------------- helpers ----------------
__device__ __forceinline__ uint32_t smem_u32(const void* p) {
    uint32_t a;
    asm("{ .reg .u64 t; cvta.to.shared.u64 t, %1; cvt.u32.u64 %0, t; }" : "=r"(a) : "l"(p));
    return a;
}
__device__ __forceinline__ void cpa16(uint32_t dst, const void* src, int sz) {
    asm volatile("cp.async.cg.shared.global [%0], [%1], 16, %2;\n"
                 :: "r"(dst), "l"(src), "r"(sz) : "memory");
}
__device__ __forceinline__ void cpa_commit() {
    asm volatile("cp.async.commit_group;\n" ::: "memory");
}
__device__ __forceinline__ void cpa_wait0() {
    asm volatile("cp.async.wait_group 0;\n" ::: "memory");
}
__device__ __forceinline__ void ldsm4(uint32_t& r0, uint32_t& r1, uint32_t& r2, uint32_t& r3,
                                      uint32_t addr) {
    asm volatile("ldmatrix.sync.aligned.m8n8.x4.shared.b16 {%0,%1,%2,%3}, [%4];"
                 : "=r"(r0), "=r"(r1), "=r"(r2), "=r"(r3) : "r"(addr));
}
__device__ __forceinline__ void mma_fp16(float* d, const uint32_t* a, uint32_t b0, uint32_t b1) {
    asm volatile("mma.sync.aligned.m16n8k16.row.col.f32.f16.f16.f32 "
                 "{%0,%1,%2,%3}, {%4,%5,%6,%7}, {%8,%9}, {%0,%1,%2,%3};"
                 : "+f"(d[0]), "+f"(d[1]), "+f"(d[2]), "+f"(d[3])
                 : "r"(a[0]), "r"(a[1]), "r"(a[2]), "r"(a[3]), "r"(b0), "r"(b1));
}

// ---------------- prep kernels ----------------
__global__ void prep_x(const float* __restrict__ xr, const float* __restrict__ xi) {
    int t = blockIdx.x * blockDim.x + threadIdx.x;   // pixel*16 + quad
    int pix = t >> 4, q = t & 15;
    const float4 r4 = *(const float4*)(xr + (size_t)pix * CC + q * 4);
    const float4 i4 = *(const float4*)(xi + (size_t)pix * CC + q * 4);
    float v[8] = {r4.x, r4.y, r4.z, r4.w, i4.x, i4.y, i4.z, i4.w};
    unsigned short h[8], l[8];
    #pragma unroll
    for (int j = 0; j < 8; ++j) {
        __half hb = __float2half_rn(v[j]);
        __half lb = __float2half_rn(v[j] - __half2float(hb));
        h[j] = *(unsigned short*)&hb;
        l[j] = *(unsigned short*)&lb;
    }
    unsigned char* p = g_xsplit + (size_t)pix * 512;
    uint2 rh = make_uint2((uint32_t)h[0] | ((uint32_t)h[1] << 16), (uint32_t)h[2] | ((uint32_t)h[3] << 16));
    uint2 ih = make_uint2((uint32_t)h[4] | ((uint32_t)h[5] << 16), (uint32_t)h[6] | ((uint32_t)h[7] << 16));
    uint2 rl = make_uint2((uint32_t)l[0] | ((uint32_t)l[1] << 16), (uint32_t)l[2] | ((uint32_t)l[3] << 16));
    uint2 il = make_uint2((uint32_t)l[4] | ((uint32_t)l[5] << 16), (uint32_t)l[6] | ((uint32_t)l[7] << 16));
    *(uint2*)(p +   0 + q * 8) = rh;
    *(uint2*)(p + 128 + q * 8) = ih;
    *(uint2*)(p + 256 + q * 8) = rl;
    *(uint2*)(p + 384 + q * 8) = il;
}

// B image per tap: rows n=0..255, each 256B (128 k fp16), 16B chunk c at c^(n&7).
// n<128 -> real out, n>=128 -> imag.  k<64 -> xr channels, k>=64 -> xi channels.
__global__ void prep_b(const float* __restrict__ kr, const float* __restrict__ ki) {
    int idx = blockIdx.x * blockDim.x + threadIdx.x;
    if (idx >= 9 * 256 * 128) return;
    int k = idx & 127;
    int n = (idx >> 7) & 255;
    int t = idx >> 15;
    int c = k & 63;
    int f = n & 127;
    bool kSecond = k >= 64;
    bool imagOut = n >= 128;
    const float* src;
    float sign = 1.0f;
    if (!imagOut) { if (!kSecond) src = kr; else { src = ki; sign = -1.0f; } }
    else          { if (!kSecond) src = ki; else   src = kr; }
    float w = sign * src[((size_t)t * 64 + c) * 128 + f];
    __half val = __float2half_rn(w);
    uint32_t off = (uint32_t)n * 256 + (uint32_t)(((k >> 3) ^ (n & 7)) * 16) + (k & 7) * 2;
    *(__half*)(g_bimg + ((size_t)t << 16) + off) = val;
}

// ---------------- main kernel ----------------
__global__ __launch_bounds__(256, 1)
void cconv_hmma(const float* __restrict__ br, const float* __restrict__ bi,
                float* __restrict__ out)
{
    extern __shared__ unsigned char sb[];
    const uint32_t base = smem_u32(sb);

    const int tid  = threadIdx.x;
    const int lane = tid & 31;
    const int warp = tid >> 5;
    const int wm   = warp & 3;       // 0..3  -> M offset wm*32
    const int wn   = warp >> 2;      // 0..1  -> N offset wn*128
    const int h = blockIdx.x;
    const int b = blockIdx.y;

    *(float*)(sb + OFF_BIAS + tid * 4) = (tid < 128) ? br[tid] : bi[tid - 128];

    float acc[2][16][4];
    #pragma unroll
    for (int mt = 0; mt < 2; ++mt)
        #pragma unroll
        for (int nt = 0; nt < 16; ++nt)
            #pragma unroll
            for (int j = 0; j < 4; ++j) acc[mt][nt][j] = 0.f;

    // per-lane ldmatrix addressing (identical to proven R4 layout)
    const int lrow = lane & 15;
    const int lhi  = lane >> 4;
    const int lsw  = lane & 7;
    const uint32_t aRowOff0 = (uint32_t)(wm * 32 + lrow) * 256;
    const uint32_t aRowOff1 = aRowOff0 + 16 * 256;
    const uint32_t bRowBase = (uint32_t)(wn * 128 + lrow) * 256;

    auto do_pass = [&](uint32_t aOff) {
        #pragma unroll
        for (int kk = 0; kk < 8; ++kk) {
            const uint32_t swc = (uint32_t)(((2 * kk + lhi) ^ lsw) * 16);
            uint32_t a[2][4];
            ldsm4(a[0][0], a[0][1], a[0][2], a[0][3], base + aOff + aRowOff0 + swc);
            ldsm4(a[1][0], a[1][1], a[1][2], a[1][3], base + aOff + aRowOff1 + swc);
            #pragma unroll
            for (int nt2 = 0; nt2 < 8; ++nt2) {
                uint32_t r0, r1, r2, r3;
                ldsm4(r0, r1, r2, r3, base + OFF_B + bRowBase + (uint32_t)(nt2 * 16 * 256) + swc);
                mma_fp16(acc[0][2*nt2],   a[0], r0, r2);
                mma_fp16(acc[0][2*nt2+1], a[0], r1, r3);
                mma_fp16(acc[1][2*nt2],   a[1], r0, r2);
                mma_fp16(acc[1][2*nt2+1], a[1], r1, r3);
            }
        }
    };

    auto load_A = [&](int tap, uint32_t bufOff) {
        const int kh = tap / 3, kw = tap % 3;
        const int h2 = h + kh - 1;
        const bool hok = ((unsigned)h2 < (unsigned)HH);
        const unsigned char* rowbase =
            g_xsplit + ((size_t)(b * HH + (hok ? h2 : 0)) * WW) * 512;
        #pragma unroll
        for (int it = 0; it < 16; ++it) {
            int idx  = tid + it * 256;        // 0..4095
            int part = idx >> 11;             // 0 hi, 1 lo
            int rem  = idx & 2047;
            int m    = rem >> 4;
            int ch   = rem & 15;
            int w2 = m + kw - 1;
            int sz = (hok && (unsigned)w2 < (unsigned)WW) ? 16 : 0;
            int w2c = min(max(w2, 0), WW - 1);
            const void* src = rowbase + (size_t)w2c * 512 + part * 256 + ch * 16;
            uint32_t dst = base + bufOff + (uint32_t)part * 32768
                         + (uint32_t)m * 256 + (uint32_t)((ch ^ (m & 7)) * 16);
            cpa16(dst, src, sz);
        }
    };
    auto load_B = [&](int tap) {
        const unsigned char* src = g_bimg + ((size_t)tap << 16);
        #pragma unroll
        for (int it = 0; it < 16; ++it) {
            int idx = tid + it * 256;         // 0..4095
            cpa16(base + OFF_B + (uint32_t)idx * 16, src + (size_t)idx * 16, 16);
        }
    };

    // prologue: A(0) + B(0)
    load_A(0, OFF_A0);
    load_B(0);
    cpa_commit();

    #pragma unroll 1
    for (int tap = 0; tap < 9; ++tap) {
        const uint32_t abuf  = (tap & 1) ? OFF_A1 : OFF_A0;
        const uint32_t abufN = (tap & 1) ? OFF_A0 : OFF_A1;

        cpa_wait0();            // A(tap), B(tap) resident (and A(tap) prefetch drained)
        __syncthreads();

        if (tap < 8) {          // prefetch next A under this tap's compute
            load_A(tap + 1, abufN);
            cpa_commit();
        }

        do_pass(abuf);          // hi pass
        do_pass(abuf + 32768);  // lo pass

        __syncthreads();        // all warps done reading B
        if (tap < 8) {
            load_B(tap + 1);
            cpa_commit();
        }
    }

    // ---- epilogue: bias + direct stores ----
    const size_t planeStride = (size_t)BB * HH * WW * FF;
    const size_t pixrow = ((size_t)(b * HH + h) * WW) * FF;
    const float* bias_s = (const float*)(sb + OFF_BIAS);
    #pragma unroll
    for (int mt = 0; mt < 2; ++mt) {
        int r0 = wm * 32 + mt * 16 + (lane >> 2);
        #pragma unroll
        for (int nt = 0; nt < 16; ++nt) {
            int col = wn * 128 + nt * 8 + (lane & 3) * 2;
            float2 bv = *(const float2*)(bias_s + col);
            int plane = col >> 7;
            int f = col & 127;
            float* o0 = out + (size_t)plane * planeStride + pixrow + (size_t)r0 * FF + f;
            *(float2*)o0 = make_float2(acc[mt][nt][0] + bv.x, acc[mt][nt][1] + bv.y);
            *(float2*)(o0 + 8 * FF) = make_float2(acc[mt][nt][2] + bv.x, acc[mt][nt][3] + bv.y);
        }
    }
}

// ---------------- launch ----------------
extern "C" void kernel_launch(void* const* d_in, const int* in_sizes, int n_in,
                              void* d_out, int out_size) {
    const float* xr = (const float*)d_in[0];
    const float* xi = (const float*)d_in[1];
    const float* kr = (const float*)d_in[2];
    const float* ki = (const float*)d_in[3];
    const float* br = (const float*)d_in[4];
    const float* bi = (const float*)d_in[5];
    float* out = (float*)d_out;
    (void)in_sizes; (void)n_in; (void)out_size;

    cudaFuncSetAttribute(cconv_hmma, cudaFuncAttributeMaxDynamicSharedMemorySize, DYN_SMEM);

    prep_x<<<(BB * HH * WW * 16) / 256, 256>>>(xr, xi);
    prep_b<<<(9 * 256 * 128 + 255) / 256, 256>>>(kr, ki);
    cconv_hmma<<<dim3(HH, BB), 256, DYN_SMEM>>>(br, bi, out);
}